// round 7
// baseline (speedup 1.0000x reference)
#include <cuda_runtime.h>

// SpikingAttentionJAX — three kernels, no in-kernel grid sync of any kind.
// LIF scan collapses to per-token occurrence counts (per-entry updates
// commute; entry t's final state depends only on count n_t and v0[t]).
//
//   K1 k_hist : histogram token_seq -> g_count (all-zero on entry).
//   K2 k_gains: one vocab entry/thread (500x256=128000): read count, re-zero
//               inline (restores invariant for next graph replay), replay n_t
//               LIF steps, write gain (0.6 spiked / 1.0); REDUX warp top-5,
//               warp 0 merges to block top-5 -> g_cand. Ends with plain
//               stores — no fence/atomic tail.
//   K3 k_top  : single block merges 2500 candidates, writes 5 winners (1.5).
//               JAX top_k tie-break (lower index wins) via
//               key = (ordered_float(v) << 32) | ~index  (unique keys).

static constexpr float DECAY     = 0.7f;
static constexpr float THETA     = 1.0f;
static constexpr float GAIN_UP   = 1.5f;
static constexpr float GAIN_DOWN = 0.6f;
static constexpr int   KW   = 5;
static constexpr int   NT   = 256;
static constexpr int   NW   = NT / 32;
static constexpr int   MAXV = 131072;        // >= vocab (128000)
static constexpr int   MAXB = 512;           // >= K2 grid (500)

static constexpr int   TT   = 512;           // k_top threads
static constexpr int   TC   = 5;             // candidates per k_top thread
static constexpr int   TNW  = TT / 32;       // 16 warps

__device__ __align__(16) int g_count[MAXV];            // zero-init; kept zero
__device__ unsigned long long g_cand[MAXB * KW];

__device__ __forceinline__ unsigned ordered_bits(float f) {
    unsigned u = __float_as_uint(f);
    return (u & 0x80000000u) ? ~u : (u | 0x80000000u);
}

// ---------------------------------------------------------------- K1: histogram
__global__ void k_hist(const int* __restrict__ tok, int n, int vocab) {
    int i = blockIdx.x * blockDim.x + threadIdx.x;
    if (i < n) {
        int t = tok[i];
        t = t < 0 ? 0 : (t >= vocab ? vocab - 1 : t);
        atomicAdd(&g_count[t], 1);
    }
}

// ---------------------------------------------------------------- K2: gains + block top-5
__global__ __launch_bounds__(NT)
void k_gains(const float* __restrict__ v0, float* __restrict__ out, int vocab) {
    const int tid  = threadIdx.x;
    const int lane = tid & 31;
    const int wid  = tid >> 5;
    const int i    = blockIdx.x * NT + tid;      // one vocab entry per thread

    __shared__ unsigned s_val[NW * KW];
    __shared__ unsigned s_idx[NW * KW];

    unsigned uval = 0u;                          // 0 = invalid/popped sentinel
    unsigned idx  = (unsigned)i;
    if (i < vocab) {
        int   cnt = g_count[i];
        float v   = __ldg(&v0[i]);
        g_count[i] = 0;                          // restore all-zero invariant
        int s = 0;
        for (int it = 0; it < cnt; it++) {
            float vn = DECAY * v + 1.0f;
            if (vn >= THETA) { v = vn - THETA; s++; }
            else             { v = vn; }
        }
        out[i] = (s > 0) ? GAIN_DOWN : 1.0f;
        uval = ordered_bits(v);
    }

    // warp top-5: REDUX.UMAX(value) + REDUX.UMIN(index) per round
    #pragma unroll
    for (int r = 0; r < KW; r++) {
        unsigned m    = __reduce_max_sync(0xffffffffu, uval);
        unsigned cand = (uval == m) ? idx : 0xffffffffu;
        unsigned wi   = __reduce_min_sync(0xffffffffu, cand);
        if (lane == 0) { s_val[wid * KW + r] = m; s_idx[wid * KW + r] = wi; }
        if (uval == m && idx == wi) uval = 0u;
    }
    __syncthreads();

    // warp 0: merge 40 (val,idx) pairs -> block top-5 -> g_cand (plain stores)
    if (wid == 0) {
        unsigned av = s_val[lane], ai = s_idx[lane];
        unsigned bv = (lane < NW * KW - 32) ? s_val[32 + lane] : 0u;
        unsigned bi = (lane < NW * KW - 32) ? s_idx[32 + lane] : 0xffffffffu;
        #pragma unroll
        for (int r = 0; r < KW; r++) {
            bool ta = (av > bv) || (av == bv && ai < bi);
            unsigned cv = ta ? av : bv;
            unsigned ci = ta ? ai : bi;
            unsigned m    = __reduce_max_sync(0xffffffffu, cv);
            unsigned cand = (cv == m) ? ci : 0xffffffffu;
            unsigned wi   = __reduce_min_sync(0xffffffffu, cand);
            if (lane == 0)
                g_cand[blockIdx.x * KW + r] =
                    ((unsigned long long)m << 32) |
                    (unsigned long long)(0xffffffffu - wi);
            if      (av == m && ai == wi) { av = 0u; ai = 0xffffffffu; }
            else if (bv == m && bi == wi) { bv = 0u; bi = 0xffffffffu; }
        }
    }
}

// ---------------------------------------------------------------- K3: final merge
__global__ __launch_bounds__(TT)
void k_top(float* __restrict__ out, int ncand) {
    const int tid  = threadIdx.x;
    const int lane = tid & 31;
    const int wid  = tid >> 5;

    __shared__ unsigned long long s_w[TNW];
    __shared__ unsigned long long s_best;

    unsigned long long k[TC];                    // static registers, no spill
    #pragma unroll
    for (int j = 0; j < TC; j++) {
        int c = tid + j * TT;
        k[j] = (c < ncand) ? g_cand[c] : 0ull;
    }

    #pragma unroll
    for (int r = 0; r < KW; r++) {
        unsigned long long m = k[0];
        #pragma unroll
        for (int j = 1; j < TC; j++) if (k[j] > m) m = k[j];
        unsigned hv = (unsigned)(m >> 32);
        unsigned wm = __reduce_max_sync(0xffffffffu, hv);
        unsigned lo = (hv == wm) ? (unsigned)(m & 0xffffffffull) : 0u;
        unsigned wl = __reduce_max_sync(0xffffffffu, lo);  // max inv-idx = min idx
        if (lane == 0) s_w[wid] = ((unsigned long long)wm << 32) | wl;
        __syncthreads();
        if (tid == 0) {
            unsigned long long b = s_w[0];
            #pragma unroll
            for (int w = 1; w < TNW; w++) if (s_w[w] > b) b = s_w[w];
            s_best = b;
            unsigned oidx = 0xffffffffu - (unsigned)(b & 0xffffffffull);
            out[oidx] = GAIN_UP;                 // >=5 unique real candidates exist
        }
        __syncthreads();
        unsigned long long b = s_best;
        #pragma unroll
        for (int j = 0; j < TC; j++) if (k[j] == b) k[j] = 0ull;
    }
}

// ---------------------------------------------------------------- launch
extern "C" void kernel_launch(void* const* d_in, const int* in_sizes, int n_in,
                              void* d_out, int out_size) {
    const int*   tok = (const int*)d_in[0];
    const float* v0  = (const float*)d_in[1];
    const int seq   = in_sizes[0];
    const int vocab = in_sizes[1];
    float* out = (float*)d_out;

    k_hist<<<(seq + NT - 1) / NT, NT>>>(tok, seq, vocab);

    int gblocks = (vocab + NT - 1) / NT;         // 500 for vocab=128000
    if (gblocks > MAXB) gblocks = MAXB;
    k_gains<<<gblocks, NT>>>(v0, out, vocab);

    k_top<<<1, TT>>>(out, gblocks * KW);
}

// round 8
// speedup vs baseline: 1.2113x; 1.2113x over previous
#include <cuda_runtime.h>

// SpikingAttentionJAX — ONE kernel, ZERO grid synchronization.
// LIF scan collapses to per-token occurrence counts (per-entry updates
// commute; entry t's final state depends only on count n_t and v0[t]).
//
// Instead of a global histogram (which forces a grid sync or second kernel),
// each block owns a 256-entry vocab slice and histograms the ENTIRE token
// stream (32 KB, L2-broadcast across 500 blocks) into shared memory.
// Then per thread: replay n_t LIF steps from v0, write gain (0.6/1.0),
// REDUX warp top-5 -> warp0 block merge -> g_cand; done-counter: the LAST
// arriving block merges 2500 candidates and writes the 5 winners (1.5).
// JAX top_k tie-break (lower index wins) via REDUX.UMIN on index and
// packed key (value<<32 | ~index) for the final merge.

static constexpr float DECAY     = 0.7f;
static constexpr float THETA     = 1.0f;
static constexpr float GAIN_UP   = 1.5f;
static constexpr float GAIN_DOWN = 0.6f;
static constexpr int   KW   = 5;
static constexpr int   NT   = 256;
static constexpr int   NW   = NT / 32;
static constexpr int   MAXB = 512;           // >= grid (500)

__device__ unsigned long long g_cand[MAXB * KW];
__device__ unsigned g_done = 0;              // monotonic across graph replays

__device__ __forceinline__ unsigned ordered_bits(float f) {
    unsigned u = __float_as_uint(f);
    return (u & 0x80000000u) ? ~u : (u | 0x80000000u);
}

__global__ __launch_bounds__(NT)
void k_main(const int* __restrict__ tok, const float* __restrict__ v0,
            float* __restrict__ out, int seq, int vocab, int nblocks) {
    const int tid  = threadIdx.x;
    const int lane = tid & 31;
    const int wid  = tid >> 5;
    const int base = blockIdx.x * NT;            // this block's vocab slice
    const int i    = base + tid;                 // this thread's vocab entry

    __shared__ int      sh_cnt[NT];
    __shared__ unsigned s_val[NW * KW];
    __shared__ unsigned s_idx[NW * KW];
    __shared__ unsigned long long s_w[NW];
    __shared__ unsigned long long s_best;
    __shared__ unsigned s_last;

    sh_cnt[tid] = 0;
    __syncthreads();

    // ---- local histogram of the whole token stream for this vocab slice ----
    // seq = 8192 -> 2048 int4; thread reads 8 int4, coalesced, L2-broadcast.
    const int4* tok4 = reinterpret_cast<const int4*>(tok);
    const int   n4   = seq >> 2;
    for (int c = tid; c < n4; c += NT) {
        int4 t4 = __ldg(&tok4[c]);
        int t;
        t = t4.x; t = t < 0 ? 0 : (t >= vocab ? vocab - 1 : t);
        if ((unsigned)(t - base) < (unsigned)NT) atomicAdd(&sh_cnt[t - base], 1);
        t = t4.y; t = t < 0 ? 0 : (t >= vocab ? vocab - 1 : t);
        if ((unsigned)(t - base) < (unsigned)NT) atomicAdd(&sh_cnt[t - base], 1);
        t = t4.z; t = t < 0 ? 0 : (t >= vocab ? vocab - 1 : t);
        if ((unsigned)(t - base) < (unsigned)NT) atomicAdd(&sh_cnt[t - base], 1);
        t = t4.w; t = t < 0 ? 0 : (t >= vocab ? vocab - 1 : t);
        if ((unsigned)(t - base) < (unsigned)NT) atomicAdd(&sh_cnt[t - base], 1);
    }
    // tail (seq not multiple of 4)
    for (int c = (n4 << 2) + tid; c < seq; c += NT) {
        int t = __ldg(&tok[c]);
        t = t < 0 ? 0 : (t >= vocab ? vocab - 1 : t);
        if ((unsigned)(t - base) < (unsigned)NT) atomicAdd(&sh_cnt[t - base], 1);
    }
    __syncthreads();

    // ---- LIF replay + gains ----
    unsigned uval = 0u;                          // 0 = invalid/popped sentinel
    unsigned idx  = (unsigned)i;
    if (i < vocab) {
        int   cnt = sh_cnt[tid];
        float v   = __ldg(&v0[i]);
        int s = 0;
        for (int it = 0; it < cnt; it++) {
            float vn = DECAY * v + 1.0f;
            if (vn >= THETA) { v = vn - THETA; s++; }
            else             { v = vn; }
        }
        out[i] = (s > 0) ? GAIN_DOWN : 1.0f;
        uval = ordered_bits(v);
    }

    // ---- warp top-5: REDUX.UMAX(value) + REDUX.UMIN(index) per round ----
    #pragma unroll
    for (int r = 0; r < KW; r++) {
        unsigned m    = __reduce_max_sync(0xffffffffu, uval);
        unsigned cand = (uval == m) ? idx : 0xffffffffu;
        unsigned wi   = __reduce_min_sync(0xffffffffu, cand);
        if (lane == 0) { s_val[wid * KW + r] = m; s_idx[wid * KW + r] = wi; }
        if (uval == m && idx == wi) uval = 0u;
    }
    __syncthreads();

    // ---- warp 0: merge 40 (val,idx) -> block top-5 -> g_cand ----
    if (wid == 0) {
        unsigned av = s_val[lane], ai = s_idx[lane];
        unsigned bv = (lane < NW * KW - 32) ? s_val[32 + lane] : 0u;
        unsigned bi = (lane < NW * KW - 32) ? s_idx[32 + lane] : 0xffffffffu;
        #pragma unroll
        for (int r = 0; r < KW; r++) {
            bool ta = (av > bv) || (av == bv && ai < bi);
            unsigned cv = ta ? av : bv;
            unsigned ci = ta ? ai : bi;
            unsigned m    = __reduce_max_sync(0xffffffffu, cv);
            unsigned cand = (cv == m) ? ci : 0xffffffffu;
            unsigned wi   = __reduce_min_sync(0xffffffffu, cand);
            if (lane == 0)
                g_cand[blockIdx.x * KW + r] =
                    ((unsigned long long)m << 32) |
                    (unsigned long long)(0xffffffffu - wi);
            if      (av == m && ai == wi) { av = 0u; ai = 0xffffffffu; }
            else if (bv == m && bi == wi) { bv = 0u; bi = 0xffffffffu; }
        }
    }

    // ---- done-counter: last-arriving block merges (no spinning) ----
    if (tid == 0) {
        __threadfence();                         // publish g_cand
        unsigned old = atomicAdd(&g_done, 1);
        s_last = (((old + 1) % (unsigned)nblocks) == 0u) ? 1u : 0u;
    }
    __syncthreads();
    if (!s_last) return;
    __threadfence();                             // acquire g_cand writes

    const int ncand = nblocks * KW;              // 2500
    unsigned long long k[10];
    #pragma unroll
    for (int j = 0; j < 10; j++) {
        int c = tid + j * NT;
        k[j] = (c < ncand) ? g_cand[c] : 0ull;
    }
    __syncthreads();

    #pragma unroll
    for (int r = 0; r < KW; r++) {
        unsigned long long m = k[0];
        #pragma unroll
        for (int j = 1; j < 10; j++) if (k[j] > m) m = k[j];
        unsigned hv = (unsigned)(m >> 32);
        unsigned wm = __reduce_max_sync(0xffffffffu, hv);
        unsigned lo = (hv == wm) ? (unsigned)(m & 0xffffffffull) : 0u;
        unsigned wl = __reduce_max_sync(0xffffffffu, lo);  // max ~idx = min idx
        if (lane == 0) s_w[wid] = ((unsigned long long)wm << 32) | wl;
        __syncthreads();
        if (tid == 0) {
            unsigned long long b = s_w[0];
            #pragma unroll
            for (int w = 1; w < NW; w++) if (s_w[w] > b) b = s_w[w];
            s_best = b;
            unsigned oidx = 0xffffffffu - (unsigned)(b & 0xffffffffull);
            out[oidx] = GAIN_UP;                 // >=5 unique real keys exist
        }
        __syncthreads();
        unsigned long long b = s_best;
        #pragma unroll
        for (int j = 0; j < 10; j++) if (k[j] == b) k[j] = 0ull;
    }
}

// ---------------------------------------------------------------- launch
extern "C" void kernel_launch(void* const* d_in, const int* in_sizes, int n_in,
                              void* d_out, int out_size) {
    const int*   tok = (const int*)d_in[0];
    const float* v0  = (const float*)d_in[1];
    const int seq   = in_sizes[0];
    const int vocab = in_sizes[1];
    float* out = (float*)d_out;

    int gblocks = (vocab + NT - 1) / NT;         // 500 for vocab=128000
    if (gblocks > MAXB) gblocks = MAXB;          // never hit at this size
    k_main<<<gblocks, NT>>>(tok, v0, out, seq, vocab, gblocks);
}